// round 10
// baseline (speedup 1.0000x reference)
#include <cuda_runtime.h>
#include <cuda_bf16.h>
#include <cuda_fp16.h>

#define N_NODES 50000
#define E_CAP   700000
#define HEADS   4
#define OUT_CH  16
#define OUT_NEU 32
#define IN_CH   128
#define HID     128   // HEADS*OUT_NEU

// ---- output layout (flat concat of reference return tuple, fp32) ----
#define OFF_OUT    0
#define OFF_IXZ    (N_NODES * 64)                  // 3,200,000
#define OFF_SCALAR (OFF_IXZ + N_NODES)             // 3,250,000
#define OFF_MEAN   (OFF_SCALAR + 1)                // 3,250,001 (ODD -> no vector stores!)
#define OFF_STD    (OFF_MEAN + N_NODES * 64)       // 6,450,001 (ODD -> no vector stores!)

// ---- scratch (device globals; no allocation allowed) ----
__device__ __align__(16) __half g_h16[N_NODES * HID];  // node features (fp16)
__device__ __align__(16) float  g_aI[N_NODES * HEADS]; // h . att_i (fp32-exact)
__device__ __align__(16) float  g_aJ[N_NODES * HEADS]; // h . att_j (fp32-exact)
__device__ int g_deg[N_NODES];
__device__ int g_start[N_NODES + 1];
__device__ int g_cursor[N_NODES];
__device__ int g_csr_src[E_CAP];

__device__ __forceinline__ void red_add_f32(float* gptr, float a) {
    asm volatile("red.global.add.f32 [%0], %1;" :: "l"(gptr), "f"(a) : "memory");
}
__device__ __forceinline__ float lrelu(float a) {
    return a > 0.0f ? a : 0.2f * a;
}

// ------------------------------ K1: zero deg + zero ixz region + scalar output
__global__ void zero_kernel(float* __restrict__ out) {
    int i = blockIdx.x * blockDim.x + threadIdx.x;
    if (i < N_NODES) {
        g_deg[i] = 0;
        out[OFF_IXZ + i] = 0.0f;   // gather kernel red-adds into this each replay
    }
    if (i == 0) out[OFF_SCALAR] = 0.0f;
}

// ------------------------------ K2: degree histogram
__global__ void hist_kernel(const int* __restrict__ dst, int E) {
    int e = blockIdx.x * blockDim.x + threadIdx.x;
    if (e < E) atomicAdd(&g_deg[dst[e]], 1);
}

// ------------------------------ K3: exclusive scan (1 block)
__global__ __launch_bounds__(1024) void scan_kernel() {
    __shared__ int warpsum[32];
    const int T = 1024;
    const int CH = (N_NODES + T - 1) / T;   // 49
    int t = threadIdx.x;
    int lo = t * CH;
    int hi = lo + CH; if (hi > N_NODES) hi = N_NODES;

    int s = 0;
    for (int i = lo; i < hi; i++) s += g_deg[i];

    int lane = t & 31, wid = t >> 5;
    int v = s;
#pragma unroll
    for (int o = 1; o < 32; o <<= 1) {
        int nv = __shfl_up_sync(0xffffffffu, v, o);
        if (lane >= o) v += nv;
    }
    if (lane == 31) warpsum[wid] = v;
    __syncthreads();
    if (wid == 0) {
        int w = warpsum[lane];
#pragma unroll
        for (int o = 1; o < 32; o <<= 1) {
            int nw = __shfl_up_sync(0xffffffffu, w, o);
            if (lane >= o) w += nw;
        }
        warpsum[lane] = w;
    }
    __syncthreads();

    int excl = v - s + (wid ? warpsum[wid - 1] : 0);
    int run = excl;
    for (int i = lo; i < hi; i++) {
        int d = g_deg[i];
        g_start[i]  = run;
        g_cursor[i] = run;
        run += d;
    }
    if (t == T - 1) g_start[N_NODES] = run;
}

// ------------------------------ K4 (profiled): register-blocked GEMM, BM=64
// 256 threads (16x16); thread (ty,tx) computes rows ty*4..+3,
// cols {tx*4..+3, 64+tx*4..+3} -> 4x8 = 32 accumulators.
// smem: sW 64KB + sXT 128x68x4 = 34.8KB -> 98.8KB -> 2 blocks/SM (25% occ).
#define BM 64
#define XPITCH 68
#define GEMM_SMEM ((IN_CH * HID + IN_CH * XPITCH) * 4)

__global__ __launch_bounds__(256, 2) void gemm_kernel(
    const float* __restrict__ x, const float* __restrict__ w,
    const float* __restrict__ att)
{
    extern __shared__ float sm[];
    float* sW  = sm;                  // [k][col] pitch 128
    float* sXT = sm + IN_CH * HID;    // [k][row] pitch 68

    const int tid = threadIdx.x;
    const int tx = tid & 15, ty = tid >> 4;
    const int row0 = blockIdx.x * BM;

    for (int i = tid; i < IN_CH * HID / 4; i += 256)
        ((float4*)sW)[i] = ((const float4*)w)[i];
    for (int i = tid; i < BM * IN_CH; i += 256) {
        int r = i >> 7, k = i & 127;
        int row = row0 + r;
        sXT[k * XPITCH + r] = (row < N_NODES) ? x[row * IN_CH + k] : 0.0f;
    }
    __syncthreads();

    float aA[16], aB[16];   // [row i][col j] for col groups A (tx*4) and B (64+tx*4)
#pragma unroll
    for (int i = 0; i < 16; i++) { aA[i] = aB[i] = 0.f; }

#pragma unroll 4
    for (int k = 0; k < IN_CH; k++) {
        const float4 xA = *(const float4*)&sXT[k * XPITCH + ty * 4];
        const float4 wA = *(const float4*)&sW[k * HID + tx * 4];
        const float4 wB = *(const float4*)&sW[k * HID + 64 + tx * 4];
        const float xa[4] = {xA.x, xA.y, xA.z, xA.w};
        const float wa[4] = {wA.x, wA.y, wA.z, wA.w};
        const float wb[4] = {wB.x, wB.y, wB.z, wB.w};
#pragma unroll
        for (int i = 0; i < 4; i++) {
#pragma unroll
            for (int j = 0; j < 4; j++) {
                aA[i * 4 + j] = fmaf(xa[i], wa[j], aA[i * 4 + j]);
                aB[i * 4 + j] = fmaf(xa[i], wb[j], aB[i * 4 + j]);
            }
        }
    }

    // ---- epilogue: store h (fp16) + attention dots ----
    const int hA = tx >> 3;            // head for group A (0/1); group B head = 2+hA
    const int cbase = tx * 4;
    float attIA[4], attJA[4], attIB[4], attJB[4];
#pragma unroll
    for (int j = 0; j < 4; j++) {
        int lA = (cbase + j) & 31;
        attIA[j] = __ldg(&att[hA * 64 + lA]);
        attJA[j] = __ldg(&att[hA * 64 + 32 + lA]);
        attIB[j] = __ldg(&att[(2 + hA) * 64 + lA]);
        attJB[j] = __ldg(&att[(2 + hA) * 64 + 32 + lA]);
    }

#pragma unroll
    for (int i = 0; i < 4; i++) {
        const int row = row0 + ty * 4 + i;
        const bool ok = (row < N_NODES);

        if (ok) {
            __half2 p0 = __floats2half2_rn(aA[i * 4 + 0], aA[i * 4 + 1]);
            __half2 p1 = __floats2half2_rn(aA[i * 4 + 2], aA[i * 4 + 3]);
            __half2 q0 = __floats2half2_rn(aB[i * 4 + 0], aB[i * 4 + 1]);
            __half2 q1 = __floats2half2_rn(aB[i * 4 + 2], aB[i * 4 + 3]);
            *(__half2*)&g_h16[row * HID + cbase]          = p0;
            *(__half2*)&g_h16[row * HID + cbase + 2]      = p1;
            *(__half2*)&g_h16[row * HID + 64 + cbase]     = q0;
            *(__half2*)&g_h16[row * HID + 64 + cbase + 2] = q1;
        }

        float sIA = 0.f, sJA = 0.f, sIB = 0.f, sJB = 0.f;
#pragma unroll
        for (int j = 0; j < 4; j++) {
            sIA = fmaf(aA[i * 4 + j], attIA[j], sIA);
            sJA = fmaf(aA[i * 4 + j], attJA[j], sJA);
            sIB = fmaf(aB[i * 4 + j], attIB[j], sIB);
            sJB = fmaf(aB[i * 4 + j], attJB[j], sJB);
        }
#pragma unroll
        for (int o = 1; o < 8; o <<= 1) {    // reduce over 8-lane tx subgroup
            sIA += __shfl_xor_sync(0xffffffffu, sIA, o);
            sJA += __shfl_xor_sync(0xffffffffu, sJA, o);
            sIB += __shfl_xor_sync(0xffffffffu, sIB, o);
            sJB += __shfl_xor_sync(0xffffffffu, sJB, o);
        }
        if (ok && (tx & 7) == 0) {
            g_aI[row * HEADS + hA]     = sIA;
            g_aJ[row * HEADS + hA]     = sJA;
            g_aI[row * HEADS + 2 + hA] = sIB;
            g_aJ[row * HEADS + 2 + hA] = sJB;
        }
    }
}

// ------------------------------ K5: scatter src into CSR slots
__global__ void scatter_kernel(const int* __restrict__ src,
                               const int* __restrict__ dst, int E) {
    int e = blockIdx.x * blockDim.x + threadIdx.x;
    if (e >= E) return;
    int pos = atomicAdd(&g_cursor[dst[e]], 1);
    g_csr_src[pos] = src[e];
}

// ------------------------------ K6: gather + softmax + VIB epilogue (atomic-free)
// 2 warps per node; warp 'half' covers channels [half*64, half*64+64).
// Lane owns 2 channels via one half2 load (128B per warp per edge).
// Unnormalized accumulation: e/(den+eps) is scale invariant (validated R4-R9).
// 2-stage software pipeline: edge j+1's loads issued before processing edge j.
__global__ __launch_bounds__(256) void gather_kernel(
    const float* __restrict__ bias, float* __restrict__ out)
{
    const int gw = (blockIdx.x * 256 + threadIdx.x) >> 5;
    const int lane = threadIdx.x & 31;
    const int n = gw >> 1, half = gw & 1;
    if (n >= N_NODES) return;

    const int ch = half * 64 + lane * 2;   // this lane's 2 channels
    const int head = ch >> 5;
    const float aIh = __ldg(&g_aI[n * 4 + head]);
    const int beg = g_start[n], end = g_start[n + 1];

    float2 acc = make_float2(0.f, 0.f);
    float den = 0.f;

    if (beg < end) {
        int s0 = __ldg(&g_csr_src[beg]);
        float aj0 = __ldg(&g_aJ[s0 * 4 + head]);
        __half2 hv0 = *(const __half2*)&g_h16[s0 * HID + ch];

        for (int j = beg; j < end; j++) {
            const int jn = (j + 1 < end) ? j + 1 : j;
            const int s1 = __ldg(&g_csr_src[jn]);
            const float aj1 = __ldg(&g_aJ[s1 * 4 + head]);
            const __half2 hv1 = *(const __half2*)&g_h16[s1 * HID + ch];

            const float e = __expf(lrelu(aIh + aj0));
            const float2 f = __half22float2(hv0);
            den += e;
            acc.x = fmaf(f.x, e, acc.x);
            acc.y = fmaf(f.y, e, acc.y);

            s0 = s1; aj0 = aj1; hv0 = hv1;
        }
    }

    const float inv = 1.0f / (den + 1e-16f);
    acc.x *= inv; acc.y *= inv;

    const int c = ch & 31;
    const float b0 = __ldg(&bias[ch]), b1 = __ldg(&bias[ch + 1]);
    float kl;
    if (c < 16) {
        const float m0 = acc.x + b0, m1 = acc.y + b1;
        const int o1 = n * 64 + head * 16 + c;
        *(float2*)&out[OFF_OUT + o1] = make_float2(m0, m1);  // 8B-aligned region
        out[OFF_MEAN + o1]     = m0;                          // odd offset: scalar
        out[OFF_MEAN + o1 + 1] = m1;
        kl = 0.5f * (m0 * m0 + m1 * m1);
    } else {
        const float sp0 = acc.x + b0 - 5.0f, sp1 = acc.y + b1 - 5.0f;
        const float st0 = fmaxf(sp0, 0.f) + log1pf(expf(-fabsf(sp0))) + 1e-10f;
        const float st1 = fmaxf(sp1, 0.f) + log1pf(expf(-fabsf(sp1))) + 1e-10f;
        const int o2 = n * 64 + head * 16 + (c - 16);
        out[OFF_STD + o2]     = st0;                          // odd offset: scalar
        out[OFF_STD + o2 + 1] = st1;
        kl = (-logf(st0) + 0.5f * st0 * st0 - 0.5f)
           + (-logf(st1) + 0.5f * st1 * st1 - 0.5f);
    }
#pragma unroll
    for (int o = 16; o; o >>= 1) kl += __shfl_xor_sync(0xffffffffu, kl, o);
    if (lane == 0) red_add_f32(&out[OFF_IXZ + n], kl * 0.25f);
}

// ---------------------------------------------------------------- launch
extern "C" void kernel_launch(void* const* d_in, const int* in_sizes, int n_in,
                              void* d_out, int out_size)
{
    const float* x    = (const float*)d_in[0];
    const int*   ei   = (const int*)d_in[1];
    const float* w    = (const float*)d_in[2];
    const float* att  = (const float*)d_in[3];
    const float* bias = (const float*)d_in[4];
    float* out = (float*)d_out;

    const int E = in_sizes[1] / 2;
    const int* src = ei;
    const int* dst = ei + E;

    cudaFuncSetAttribute(gemm_kernel,
                         cudaFuncAttributeMaxDynamicSharedMemorySize, GEMM_SMEM);

    const int eb = (E + 255) / 256;
    // launch order: gemm is #4 (ncu profiles launch #4)
    zero_kernel<<<(N_NODES + 255) / 256, 256>>>(out);
    hist_kernel<<<eb, 256>>>(dst, E);
    scan_kernel<<<1, 1024>>>();
    gemm_kernel<<<(N_NODES + BM - 1) / BM, 256, GEMM_SMEM>>>(x, w, att);
    scatter_kernel<<<eb, 256>>>(src, dst, E);
    gather_kernel<<<(N_NODES * 2 * 32 + 255) / 256, 256>>>(bias, out);
}

// round 11
// speedup vs baseline: 1.3795x; 1.3795x over previous
#include <cuda_runtime.h>
#include <cuda_bf16.h>
#include <cuda_fp16.h>

#define N_NODES 50000
#define E_CAP   700000
#define HEADS   4
#define OUT_CH  16
#define OUT_NEU 32
#define IN_CH   128
#define HID     128   // HEADS*OUT_NEU

// ---- output layout (flat concat of reference return tuple, fp32) ----
#define OFF_OUT    0
#define OFF_IXZ    (N_NODES * 64)                  // 3,200,000
#define OFF_SCALAR (OFF_IXZ + N_NODES)             // 3,250,000
#define OFF_MEAN   (OFF_SCALAR + 1)                // 3,250,001 (ODD -> no vector stores!)
#define OFF_STD    (OFF_MEAN + N_NODES * 64)       // 6,450,001 (ODD -> no vector stores!)

// ---- scratch (device globals; no allocation allowed) ----
__device__ __align__(16) __half g_h16[N_NODES * HID];  // node features (fp16)
__device__ __align__(16) float  g_agg[N_NODES * HID];  // UNNORMALIZED segment-sum (fp32)
__device__ __align__(16) float  g_aI[N_NODES * HEADS]; // h . att_i (fp32-exact)
__device__ __align__(16) float  g_aJ[N_NODES * HEADS]; // h . att_j (fp32-exact)
__device__ __align__(16) float  g_denom[N_NODES * HEADS];

__device__ __forceinline__ void red_add_v4(float* gptr, float a, float b, float c, float d) {
    asm volatile("red.global.add.v4.f32 [%0], {%1, %2, %3, %4};"
                 :: "l"(gptr), "f"(a), "f"(b), "f"(c), "f"(d) : "memory");
}
__device__ __forceinline__ void red_add_f32(float* gptr, float a) {
    asm volatile("red.global.add.f32 [%0], %1;" :: "l"(gptr), "f"(a) : "memory");
}
__device__ __forceinline__ float lrelu(float a) {
    return a > 0.0f ? a : 0.2f * a;
}

// ---------------------------------------------------------------- K1: zero agg
__global__ void zero_agg_kernel() {
    int i = blockIdx.x * blockDim.x + threadIdx.x;
    int stride = gridDim.x * blockDim.x;
    float4 z = make_float4(0.f, 0.f, 0.f, 0.f);
    for (int k = i; k < N_NODES * HID / 4; k += stride)
        ((float4*)g_agg)[k] = z;
}
// ---------------------------------------------------------------- K2: zero denom + scalar
__global__ void zero_denom_kernel(float* __restrict__ out) {
    int i = blockIdx.x * blockDim.x + threadIdx.x;
    if (i < N_NODES)
        ((float4*)g_denom)[i] = make_float4(0.f, 0.f, 0.f, 0.f);
    if (i == 0) out[OFF_SCALAR] = 0.0f;
}

// ------------------- K3: register-blocked GEMM, BM=64, K-chunked (KC=64)
// 256 threads (16x16); thread (ty,tx) computes rows ty*4..+3,
// cols {tx*4..+3, 64+tx*4..+3} -> 32 accumulators, persisting across 2 k-chunks.
// smem per chunk: sW [64][128] = 32KB + sXT [64][68] = 17.4KB -> 49.4KB
// -> 3 blocks/SM (launch_bounds(256,3)), 24 warps/SM (~50% occ).
#define BM 64
#define KC 64
#define XPITCH 68
#define GEMM_SMEM ((KC * HID + KC * XPITCH) * 4)   // 49.4 KB

__global__ __launch_bounds__(256, 3) void gemm_kernel(
    const float* __restrict__ x, const float* __restrict__ w,
    const float* __restrict__ att)
{
    extern __shared__ float sm[];
    float* sW  = sm;               // [kk][col] pitch 128
    float* sXT = sm + KC * HID;    // [kk][row] pitch 68

    const int tid = threadIdx.x;
    const int tx = tid & 15, ty = tid >> 4;
    const int row0 = blockIdx.x * BM;

    float aA[16], aB[16];   // [row i][col j] for col groups A (tx*4) and B (64+tx*4)
#pragma unroll
    for (int i = 0; i < 16; i++) { aA[i] = aB[i] = 0.f; }

#pragma unroll
    for (int k0 = 0; k0 < IN_CH; k0 += KC) {
        if (k0 > 0) __syncthreads();   // protect smem reuse

        // W chunk: rows k0..k0+63, all 128 cols (contiguous -> float4 copy)
        const float4* wsrc = (const float4*)(w + k0 * HID);
        for (int i = tid; i < KC * HID / 4; i += 256)
            ((float4*)sW)[i] = wsrc[i];
        // X chunk transpose: sXT[kk][r] = x[row0+r][k0+kk]
        for (int i = tid; i < BM * KC; i += 256) {
            int r = i >> 6, kk = i & 63;
            int row = row0 + r;
            sXT[kk * XPITCH + r] = (row < N_NODES) ? x[row * IN_CH + k0 + kk] : 0.0f;
        }
        __syncthreads();

#pragma unroll 4
        for (int kk = 0; kk < KC; kk++) {
            const float4 xA = *(const float4*)&sXT[kk * XPITCH + ty * 4];
            const float4 wA = *(const float4*)&sW[kk * HID + tx * 4];
            const float4 wB = *(const float4*)&sW[kk * HID + 64 + tx * 4];
            const float xa[4] = {xA.x, xA.y, xA.z, xA.w};
            const float wa[4] = {wA.x, wA.y, wA.z, wA.w};
            const float wb[4] = {wB.x, wB.y, wB.z, wB.w};
#pragma unroll
            for (int i = 0; i < 4; i++) {
#pragma unroll
                for (int j = 0; j < 4; j++) {
                    aA[i * 4 + j] = fmaf(xa[i], wa[j], aA[i * 4 + j]);
                    aB[i * 4 + j] = fmaf(xa[i], wb[j], aB[i * 4 + j]);
                }
            }
        }
    }

    // ---- epilogue: store h (fp16) + attention dots ----
    const int hA = tx >> 3;            // head for group A (0/1); group B head = 2+hA
    const int cbase = tx * 4;
    float attIA[4], attJA[4], attIB[4], attJB[4];
#pragma unroll
    for (int j = 0; j < 4; j++) {
        int lA = (cbase + j) & 31;
        attIA[j] = __ldg(&att[hA * 64 + lA]);
        attJA[j] = __ldg(&att[hA * 64 + 32 + lA]);
        attIB[j] = __ldg(&att[(2 + hA) * 64 + lA]);
        attJB[j] = __ldg(&att[(2 + hA) * 64 + 32 + lA]);
    }

#pragma unroll
    for (int i = 0; i < 4; i++) {
        const int row = row0 + ty * 4 + i;
        const bool ok = (row < N_NODES);

        if (ok) {
            __half2 p0 = __floats2half2_rn(aA[i * 4 + 0], aA[i * 4 + 1]);
            __half2 p1 = __floats2half2_rn(aA[i * 4 + 2], aA[i * 4 + 3]);
            __half2 q0 = __floats2half2_rn(aB[i * 4 + 0], aB[i * 4 + 1]);
            __half2 q1 = __floats2half2_rn(aB[i * 4 + 2], aB[i * 4 + 3]);
            *(__half2*)&g_h16[row * HID + cbase]          = p0;
            *(__half2*)&g_h16[row * HID + cbase + 2]      = p1;
            *(__half2*)&g_h16[row * HID + 64 + cbase]     = q0;
            *(__half2*)&g_h16[row * HID + 64 + cbase + 2] = q1;
        }

        float sIA = 0.f, sJA = 0.f, sIB = 0.f, sJB = 0.f;
#pragma unroll
        for (int j = 0; j < 4; j++) {
            sIA = fmaf(aA[i * 4 + j], attIA[j], sIA);
            sJA = fmaf(aA[i * 4 + j], attJA[j], sJA);
            sIB = fmaf(aB[i * 4 + j], attIB[j], sIB);
            sJB = fmaf(aB[i * 4 + j], attJB[j], sJB);
        }
#pragma unroll
        for (int o = 1; o < 8; o <<= 1) {    // reduce over 8-lane tx subgroup
            sIA += __shfl_xor_sync(0xffffffffu, sIA, o);
            sJA += __shfl_xor_sync(0xffffffffu, sJA, o);
            sIB += __shfl_xor_sync(0xffffffffu, sIB, o);
            sJB += __shfl_xor_sync(0xffffffffu, sJB, o);
        }
        if (ok && (tx & 7) == 0) {
            g_aI[row * HEADS + hA]     = sIA;
            g_aJ[row * HEADS + hA]     = sJA;
            g_aI[row * HEADS + 2 + hA] = sIB;
            g_aJ[row * HEADS + 2 + hA] = sJB;
        }
    }
}

// ------- K4 (profiled): FUSED edge pass (fp16 h): e = exp(leaky(aI[d]+aJ[s]));
//         agg[dst] += e * h[src]; denom[dst] += e
// 16 threads per edge; lane -> (head = lane>>2, 8-channel chunk = lane&3)
// No max subtraction: e/(denom+eps) is scale invariant (validated R4-R10).
__global__ void edge_fused(const int* __restrict__ src,
                           const int* __restrict__ dst, int E)
{
    int g = blockIdx.x * blockDim.x + threadIdx.x;
    int e = g >> 4;
    if (e >= E) return;
    int lane = g & 15;
    int s = src[e], d = dst[e];
    int head = lane >> 2;
    float aih = __ldg(&g_aI[d * 4 + head]);
    float ajh = __ldg(&g_aJ[s * 4 + head]);
    float ev = __expf(lrelu(aih + ajh));

    const uint4 hv = *(const uint4*)&g_h16[s * HID + lane * 8];
    float2 f0 = __half22float2(*(const half2*)&hv.x);
    float2 f1 = __half22float2(*(const half2*)&hv.y);
    float2 f2 = __half22float2(*(const half2*)&hv.z);
    float2 f3 = __half22float2(*(const half2*)&hv.w);

    float* base = &g_agg[d * HID + lane * 8];
    red_add_v4(base,     f0.x * ev, f0.y * ev, f1.x * ev, f1.y * ev);
    red_add_v4(base + 4, f2.x * ev, f2.y * ev, f3.x * ev, f3.y * ev);
    if ((lane & 3) == 0)
        red_add_f32(&g_denom[d * 4 + head], ev);
}

// ----------------------------------- K5: VIB epilogue (+ normalization) + outputs
__global__ __launch_bounds__(256) void finalize_kernel(
    const float* __restrict__ bias, float* __restrict__ out)
{
    int warp = threadIdx.x >> 5, lane = threadIdx.x & 31;
    int n = blockIdx.x * 8 + warp;
    if (n >= N_NODES) return;
    int head = lane >> 3, cc = lane & 7;

    const float inv = 1.0f / (__ldg(&g_denom[n * 4 + head]) + 1e-16f);

    float kl = 0.0f;
#pragma unroll
    for (int t = 0; t < 2; t++) {
        int c = cc + t * 8;
        float mv = g_agg[n * HID + head * 32 + c] * inv + bias[head * 32 + c];
        float sp = g_agg[n * HID + head * 32 + 16 + c] * inv + bias[head * 32 + 16 + c] - 5.0f;
        float st = fmaxf(sp, 0.0f) + log1pf(expf(-fabsf(sp))) + 1e-10f;
        kl += -logf(st) + 0.5f * (st * st + mv * mv) - 0.5f;
        out[OFF_OUT  + n * 64 + head * 16 + c] = mv;
        out[OFF_MEAN + n * 64 + head * 16 + c] = mv;
        out[OFF_STD  + n * 64 + head * 16 + c] = st;
    }
#pragma unroll
    for (int o = 16; o; o >>= 1) kl += __shfl_xor_sync(0xffffffffu, kl, o);
    if (lane == 0) out[OFF_IXZ + n] = kl * 0.25f;
}

// ---------------------------------------------------------------- launch
extern "C" void kernel_launch(void* const* d_in, const int* in_sizes, int n_in,
                              void* d_out, int out_size)
{
    const float* x    = (const float*)d_in[0];
    const int*   ei   = (const int*)d_in[1];
    const float* w    = (const float*)d_in[2];
    const float* att  = (const float*)d_in[3];
    const float* bias = (const float*)d_in[4];
    float* out = (float*)d_out;

    const int E = in_sizes[1] / 2;
    const int* src = ei;
    const int* dst = ei + E;

    cudaFuncSetAttribute(gemm_kernel,
                         cudaFuncAttributeMaxDynamicSharedMemorySize, GEMM_SMEM);

    // launch order: edge_fused is #4 (ncu profiles launch #4)
    zero_agg_kernel<<<512, 256>>>();
    zero_denom_kernel<<<(N_NODES + 255) / 256, 256>>>(out);
    gemm_kernel<<<(N_NODES + BM - 1) / BM, 256, GEMM_SMEM>>>(x, w, att);
    edge_fused<<<(E * 16 + 255) / 256, 256>>>(src, dst, E);
    finalize_kernel<<<(N_NODES + 7) / 8, 256>>>(bias, out);
}